// round 10
// baseline (speedup 1.0000x reference)
#include <cuda_runtime.h>
#include <cstddef>
#include <cstdint>
#include <math.h>

// CTC batch cost (Keras semantics): B=256, T=512, V=256, L=64, blank=V-1
// loss[b] = -log P(y_true[b] | y_pred[b]), logp = log(y_pred + 1e-7)
//
// R9: bidirectional meet-in-the-middle DP (R8, proven: P = sum_s
// alpha_255(s)*B_256(s)) + SAME-WARP cp.async gather pipeline.
//   R8 residual limiter: per-warp outstanding-LDG cap (~55) left in-flight
//   bytes at ~0.9MB chip-wide vs the ~2.4MB BW*latency product (DRAM 64.6%).
//   LDGSTS (cp.async) has NO depth cap: each DP warp now streams its own
//   gathers into a private 4-slot smem ring (8t x 66 floats per slot),
//   commit_group per chunk, wait_group 3 before consuming, slot reuse at
//   distance 4. Producer==consumer warp -> no barriers, no cross-warp
//   coupling. In-flight/warp ~200 sectors -> ~3.3MB chip-wide.
//
// Layout/DP identical to R8: lane j owns Ba=s4j, La=s4j+1, Bb=s4j+2,
// Lb=s4j+3; lane31 extra B64=s128. Per-lane power-of-2 scaling, renorm
// every 8 steps, exact integer exponent bookkeeping.
// 2 elements per 128-thread block: warp0/1 = elem0 fwd/bwd, warp2/3 = elem1.

#define B_  256
#define T_  512
#define V_  256
#define L_  64
#define CH  8
#define HT  (T_ / 2)
#define NCH (HT / CH)       // 32 chunks per direction
#define NSL 4               // ring slots per warp
#define ROWF 66             // floats per timestep row (64 label cols + blank + pad)
#define EPS 1e-7f
#define FULL 0xFFFFFFFFu
#define MAXGAP 64
#define LN2F 0.6931471805599453f

__device__ __forceinline__ float exp2i(int e)
{
    if (e <= -127) return 0.0f;
    if (e > 127)   e = 127;
    return __int_as_float((e + 127) << 23);
}

__device__ __forceinline__ void cp_async4(uint32_t saddr, const float* gaddr)
{
    asm volatile("cp.async.ca.shared.global [%0], [%1], 4;\n"
                 :: "r"(saddr), "l"(gaddr) : "memory");
}

__global__ void __launch_bounds__(128)
ctc_forward_kernel(const int* __restrict__ y_true,
                   const float* __restrict__ y_pred,
                   float* __restrict__ out)
{
    __shared__ float ring[4][NSL][CH][ROWF];   // 33792 B: per-warp private rings
    __shared__ float sBv[2][32][5];            // backward B-values per element
    __shared__ int   sBo[2][32];

    const int tid   = threadIdx.x;
    const int wslot = tid >> 5;        // 0..3
    const int eidx  = wslot >> 1;      // element within block
    const int dir   = wslot & 1;       // 0 = forward, 1 = backward
    const int lane  = tid & 31;
    const int b     = blockIdx.x * 2 + eidx;

    const float* base = y_pred + (size_t)b * (size_t)(T_ * V_);
    const int* lrow = y_true + b * L_;
    const int la = lrow[2 * lane];
    const int lb = lrow[2 * lane + 1];
    const int lprev = __shfl_up_sync(FULL, lb, 1);    // label[2j-1]
    const int lnext = __shfl_down_sync(FULL, la, 1);  // label[2j+2]
    const float sa  = (la != lprev) ? 1.0f : 0.0f;    // lane0 irrelevant
    const float saN = (lnext != lb) ? 1.0f : 0.0f;    // lane31 irrelevant
    const float sb  = (lb != la) ? 1.0f : 0.0f;

    const float* dbase = dir ? base + (size_t)(T_ - 1) * V_ : base;
    const int    drow  = dir ? -V_ : V_;
    const uint32_t rbase =
        (uint32_t)__cvta_generic_to_shared(&ring[wslot][0][0][0]);

    float Ba, La_v, Bb, Lb_v, B64;
    int   off = 0;
    float corr;
    float va[CH], vb[CH], vq[CH];

    // ---- cp.async gather of one chunk (8 timesteps) into ring slot ----
#define ISSUE_CHUNK(c)                                                      \
    do {                                                                    \
        uint32_t _sp = rbase + (uint32_t)(((c) & (NSL - 1)) * (CH * ROWF * 4)); \
        const float* _r0 = dbase + (long long)(c) * CH * drow;              \
        _Pragma("unroll")                                                   \
        for (int _i = 0; _i < CH; ++_i) {                                   \
            const float* _r = _r0 + (long long)_i * drow;                   \
            cp_async4(_sp + _i * (ROWF * 4) + lane * 8,     _r + la);       \
            cp_async4(_sp + _i * (ROWF * 4) + lane * 8 + 4, _r + lb);       \
        }                                                                   \
        if (lane < CH)                                                      \
            cp_async4(_sp + lane * (ROWF * 4) + 64 * 4,                     \
                      _r0 + (long long)lane * drow + (V_ - 1));             \
        asm volatile("cp.async.commit_group;\n" ::: "memory");              \
    } while (0)

#define READ_SLOT(c)                                                        \
    do {                                                                    \
        const float (*_slab)[ROWF] =                                        \
            (const float (*)[ROWF])ring[wslot][(c) & (NSL - 1)];            \
        _Pragma("unroll")                                                   \
        for (int _i = 0; _i < CH; ++_i) {                                   \
            float2 _t = *(const float2*)(&_slab[_i][2 * lane]);             \
            va[_i] = _t.x; vb[_i] = _t.y; vq[_i] = _slab[_i][64];           \
        }                                                                   \
    } while (0)

#define WAITG(n)                                                            \
    do {                                                                    \
        asm volatile("cp.async.wait_group " #n ";\n" ::: "memory");         \
        __syncwarp();                                                       \
    } while (0)

    // ---- DP steps (identical math to R8) ----
#define STEP_F(pa_, pb_, pq_)                                       \
    do {                                                            \
        float _pa = (pa_) + EPS;                                    \
        float _pb = (pb_) + EPS;                                    \
        float _pq = (pq_) + EPS;                                    \
        float _tp = __shfl_up_sync(FULL, Lb_v, 1) * corr;           \
        float _nLa = (La_v + Ba + sa * _tp) * _pa;                  \
        float _nLb = (Lb_v + Bb + sb * La_v) * _pb;                 \
        float _nBa = (Ba + _tp) * _pq;                              \
        float _nBb = (Bb + La_v) * _pq;                             \
        float _nB6 = (B64 + Lb_v) * _pq;                            \
        La_v = _nLa; Lb_v = _nLb; Ba = _nBa; Bb = _nBb; B64 = _nB6; \
    } while (0)

#define STEP_B(pa_, pb_, pq_)                                       \
    do {                                                            \
        float _pa = (pa_) + EPS;                                    \
        float _pb = (pb_) + EPS;                                    \
        float _pq = (pq_) + EPS;                                    \
        float _nb = __shfl_down_sync(FULL, Ba, 1);                  \
        float _nl = __shfl_down_sync(FULL, La_v, 1);                \
        _nb = (lane == 31) ? B64 : _nb * corr;                      \
        _nl = (lane == 31) ? 0.0f : _nl * corr;                     \
        float _nBa = (Ba + La_v) * _pq;                             \
        float _nLa = (La_v + Bb + sb * Lb_v) * _pa;                 \
        float _nBb = (Bb + Lb_v) * _pq;                             \
        float _nLb = (Lb_v + _nb + saN * _nl) * _pb;                \
        float _nB6 = B64 * _pq;                                     \
        La_v = _nLa; Lb_v = _nLb; Ba = _nBa; Bb = _nBb; B64 = _nB6; \
    } while (0)

#define RENORM_F()                                                          \
    do {                                                                    \
        float _m = fmaxf(fmaxf(fmaxf(La_v, Lb_v), fmaxf(Ba, Bb)), B64);     \
        bool _dead = (_m <= 0.0f);                                          \
        int _iexp = _dead ? 0 : (((__float_as_int(_m) >> 23) & 255) - 127); \
        if (_iexp < -120) _iexp = -120;                                     \
        int _offnew = off + _iexp;                                          \
        int _up = __shfl_up_sync(FULL, _offnew, 1);                         \
        int _offfin;                                                        \
        if (lane == 0)      _offfin = _offnew;                              \
        else if (_dead)     _offfin = _up;                                  \
        else                _offfin = (_up - MAXGAP > _offnew)              \
                                        ? (_up - MAXGAP) : _offnew;         \
        if (!_dead) {                                                       \
            float _f = exp2i(off - _offfin);                                \
            La_v *= _f; Lb_v *= _f; Ba *= _f; Bb *= _f; B64 *= _f;          \
        }                                                                   \
        off = _offfin;                                                      \
        int _upf = __shfl_up_sync(FULL, _offfin, 1);                        \
        int _dd = _upf - _offfin;                                           \
        if (_dd > 100) _dd = 100;                                           \
        corr = (lane == 0) ? 0.0f : exp2i(_dd);                             \
    } while (0)

#define RENORM_B()                                                          \
    do {                                                                    \
        float _m = fmaxf(fmaxf(fmaxf(La_v, Lb_v), fmaxf(Ba, Bb)), B64);     \
        bool _dead = (_m <= 0.0f);                                          \
        int _iexp = _dead ? 0 : (((__float_as_int(_m) >> 23) & 255) - 127); \
        if (_iexp < -120) _iexp = -120;                                     \
        int _offnew = off + _iexp;                                          \
        int _dn = __shfl_down_sync(FULL, _offnew, 1);                       \
        int _offfin;                                                        \
        if (lane == 31)     _offfin = _offnew;                              \
        else if (_dead)     _offfin = _dn;                                  \
        else                _offfin = (_dn - MAXGAP > _offnew)              \
                                        ? (_dn - MAXGAP) : _offnew;         \
        if (!_dead) {                                                       \
            float _f = exp2i(off - _offfin);                                \
            La_v *= _f; Lb_v *= _f; Ba *= _f; Bb *= _f; B64 *= _f;          \
        }                                                                   \
        off = _offfin;                                                      \
        int _dnf = __shfl_down_sync(FULL, _offfin, 1);                      \
        int _dd = _dnf - _offfin;                                           \
        if (_dd > 100) _dd = 100;                                           \
        corr = (lane == 31) ? 0.0f : exp2i(_dd);                            \
    } while (0)

#define DO_STEPS(STEPM)                                                 \
    do {                                                                \
        _Pragma("unroll")                                               \
        for (int _s = 0; _s < CH; ++_s) STEPM(va[_s], vb[_s], vq[_s]);  \
    } while (0)

    // Pipeline: prime 4 groups; steady state waits for group c (wait_group 3
    // with 3 younger groups in flight), reads slot c, issues c+4 into the
    // just-read slot (values already in registers), then runs the DP chunk.
    // Tail iterations use wait_group 2/1/0 as the in-flight count shrinks.
#define RUN_DIR(STEPM, RENM)                                            \
    do {                                                                \
        ISSUE_CHUNK(0); ISSUE_CHUNK(1); ISSUE_CHUNK(2); ISSUE_CHUNK(3); \
        for (int c = 0; c <= NCH - 4; ++c) {                            \
            WAITG(3);                                                   \
            READ_SLOT(c);                                               \
            if (c + 4 < NCH) ISSUE_CHUNK(c + 4);                        \
            DO_STEPS(STEPM); RENM();                                    \
        }                                                               \
        WAITG(2); READ_SLOT(NCH - 3); DO_STEPS(STEPM); RENM();          \
        WAITG(1); READ_SLOT(NCH - 2); DO_STEPS(STEPM); RENM();          \
        WAITG(0); READ_SLOT(NCH - 1); DO_STEPS(STEPM); RENM();          \
    } while (0)

    if (dir == 0) {
        // -------- forward: t = 0..255 --------
        Ba = (lane == 0) ? 1.0f : 0.0f;
        La_v = Lb_v = Bb = B64 = 0.0f;
        corr = (lane == 0) ? 0.0f : 1.0f;
        RUN_DIR(STEP_F, RENORM_F);
    } else {
        // -------- backward: t = 511..256 --------
        Ba = La_v = Bb = Lb_v = 0.0f;
        B64 = (lane == 31) ? 1.0f : 0.0f;
        corr = (lane == 31) ? 0.0f : 1.0f;
        RUN_DIR(STEP_B, RENORM_B);

        // Publish B_{256}(s) = beta(s) + beta(s+1) + skip(s+2)*beta(s+2)
        {
            float _nb = __shfl_down_sync(FULL, Ba, 1);
            float _nl = __shfl_down_sync(FULL, La_v, 1);
            _nb = (lane == 31) ? B64 : _nb * corr;
            _nl = (lane == 31) ? 0.0f : _nl * corr;
            sBv[eidx][lane][0] = Ba + La_v;                // B at s=4j
            sBv[eidx][lane][1] = La_v + Bb + sb * Lb_v;    // B at s=4j+1
            sBv[eidx][lane][2] = Bb + Lb_v;                // B at s=4j+2
            sBv[eidx][lane][3] = Lb_v + _nb + saN * _nl;   // B at s=4j+3
            sBv[eidx][lane][4] = B64;                      // B at s=128
            sBo[eidx][lane] = off;
        }
    }

    __syncthreads();

    if (dir == 0) {
        // dot over this lane's states; true value = dot * 2^(offA+offB)
        float dot = Ba * sBv[eidx][lane][0] + La_v * sBv[eidx][lane][1]
                  + Bb * sBv[eidx][lane][2] + Lb_v * sBv[eidx][lane][3];
        if (lane == 31) dot += B64 * sBv[eidx][lane][4];
        int e = off + sBo[eidx][lane];

        int   ep;    // normalized exponent of lane contribution
        float m;     // mantissa in [1,2)
        if (dot > 0.0f) {
            int ie = ((__float_as_int(dot) >> 23) & 255) - 127;
            m  = dot * exp2i(-ie);
            ep = e + ie;
        } else {
            m  = 0.0f;
            ep = -0x40000000;
        }
        int emax = ep;
#pragma unroll
        for (int o = 16; o > 0; o >>= 1)
            emax = max(emax, __shfl_xor_sync(FULL, emax, o));
        float part = m * exp2i(ep - emax);
#pragma unroll
        for (int o = 16; o > 0; o >>= 1)
            part += __shfl_xor_sync(FULL, part, o);
        if (lane == 0)
            out[b] = -((__log2f(part) + (float)emax) * LN2F);
    }
}

extern "C" void kernel_launch(void* const* d_in, const int* in_sizes, int n_in,
                              void* d_out, int out_size)
{
    // Identify inputs by element count: y_true is B*L int32, y_pred is B*T*V f32
    const int* y_true = nullptr;
    const float* y_pred = nullptr;
    if (in_sizes[0] == B_ * L_) {
        y_true = (const int*)d_in[0];
        y_pred = (const float*)d_in[1];
    } else {
        y_true = (const int*)d_in[1];
        y_pred = (const float*)d_in[0];
    }
    float* out = (float*)d_out;

    // 2 elements per 128-thread block (4 warps: fwd/bwd per element, one per
    // SMSP); grid = 128 blocks
    ctc_forward_kernel<<<B_ / 2, 128>>>(y_true, y_pred, out);
}

// round 11
// speedup vs baseline: 1.1872x; 1.1872x over previous
#include <cuda_runtime.h>
#include <cstddef>
#include <cstdint>
#include <math.h>

// CTC batch cost (Keras semantics): B=256, T=512, V=256, L=64, blank=V-1
// loss[b] = -log P(y_true[b] | y_pred[b]), logp = log(y_pred + 1e-7)
//
// R11 = R8 (bidirectional meet-in-the-middle DP, best: 29.4us) + PACED
// L2-prefetch warps.
//   - R8 limiter: DP warps' gathers go to DRAM (577cyc) with a ~55
//     outstanding-LDG cap -> 0.9MB in flight chip-wide < 2.4MB BW*latency
//     product (DRAM 64.6%).
//   - R7's unpaced loaders were neutral: they streamed 134MB through the
//     126MB L2 in ~1us, evicting prefetched lines long before the 37us DP
//     consumed them. Fix = BOUNDED LEAD: loader stays <=64 rows ahead of
//     its DP warp's chunk counter (volatile smem int, DP bumps per chunk;
//     DP never waits -> zero coupling). Chip-wide prefetch-ahead = 512 dirs
//     x 64KB = 32MB << L2. DP gathers then hit L2 (~250cyc), covered by the
//     55-cap -> DP is compute-paced; wall clock ~= DRAM stream ~19us.
//
// Block = 128 threads, one element:
//   warp0: forward DP  t=0..255     warp1: backward DP  t=511..256
//   warp2: fwd loader (rows 0..255) warp3: bwd loader (rows 511..256)
// Loader: one __ldcg per row at lane*32B -> all 32 sectors of the 1KB row.
//
// DP (identical to R8): lane j owns Ba=s4j, La=s4j+1, Bb=s4j+2, Lb=s4j+3;
// lane31 extra B64=s128. Per-lane power-of-2 scaling, renorm every 8 steps,
// exact integer exponent bookkeeping. P = sum_s alpha_255(s)*B_256(s).

#define B_  256
#define T_  512
#define V_  256
#define L_  64
#define CH  8
#define HT  (T_ / 2)        // 256 steps per direction
#define NCH (HT / CH)       // 32 chunks per direction
#define LEAD 64             // loader lead bound, rows
#define EPS 1e-7f
#define FULL 0xFFFFFFFFu
#define MAXGAP 64
#define LN2F 0.6931471805599453f

__device__ __forceinline__ float exp2i(int e)
{
    if (e <= -127) return 0.0f;
    if (e > 127)   e = 127;
    return __int_as_float((e + 127) << 23);
}

__global__ void __launch_bounds__(128)
ctc_forward_kernel(const int* __restrict__ y_true,
                   const float* __restrict__ y_pred,
                   float* __restrict__ out)
{
    __shared__ float sBv[32][5];       // backward B-values per lane
    __shared__ int   sBo[32];          // backward off per lane
    __shared__ int   prog[2];          // DP chunk progress per direction

    const int b    = blockIdx.x;
    const int wid  = threadIdx.x >> 5;
    const int lane = threadIdx.x & 31;

    const float* base = y_pred + (size_t)b * (size_t)(T_ * V_);

    if (threadIdx.x < 2) prog[threadIdx.x] = 0;
    __syncthreads();

    // ================= loader warps (wid 2,3): paced L2 prefetch ==========
    if (wid >= 2) {
        const int dirL = wid - 2;                  // 0 fwd, 1 bwd
        volatile int* vp = &prog[dirL];
        // fwd rows 0,1,2,..,255 ; bwd rows 511,510,..,256
        const char* ap = (const char*)base + (size_t)lane * 32
                       + (dirL ? (size_t)(T_ - 1) * (V_ * 4) : 0);
        const long long step = dirL ? -(long long)(V_ * 4) : (V_ * 4);
        for (int r8 = 0; r8 < HT; r8 += 8) {
            // allow rows [r8, r8+8) once DP progress*8 + LEAD covers them
            while (*vp * CH + LEAD < r8 + 8) __nanosleep(200);
            const char* a = ap + (long long)r8 * step;
#pragma unroll
            for (int i = 0; i < 8; ++i) {
                unsigned v;
                asm volatile("ld.global.cg.b32 %0, [%1];"
                             : "=r"(v) : "l"(a) : "memory");
                a += step;
            }
        }
        __syncthreads();   // matches DP warps' combine barrier
        return;
    }

    // ================= DP warps (wid 0,1): identical math to R8 ===========
    const int dir = wid;               // 0 = forward, 1 = backward
    const int* lrow = y_true + b * L_;
    const int la = lrow[2 * lane];
    const int lb = lrow[2 * lane + 1];
    const int lprev = __shfl_up_sync(FULL, lb, 1);    // label[2j-1]
    const int lnext = __shfl_down_sync(FULL, la, 1);  // label[2j+2]
    const float sa  = (la != lprev) ? 1.0f : 0.0f;    // lane0 irrelevant
    const float saN = (lnext != lb) ? 1.0f : 0.0f;    // lane31 irrelevant
    const float sb  = (lb != la) ? 1.0f : 0.0f;

    volatile int* vprog = &prog[dir];

    float Ba, La_v, Bb, Lb_v, B64;
    int   off  = 0;
    float corr;

    float P0a[CH], P0b[CH], P0q[CH];
    float P1a[CH], P1b[CH], P1q[CH];
    float P2a[CH], P2b[CH], P2q[CH];
    float P3a[CH], P3b[CH], P3q[CH];

#define LOAD_CHUNK_F(pa, pb, pq, c)                                 \
    do {                                                            \
        const float* _r = base + (size_t)(c) * (CH * V_);           \
        _Pragma("unroll")                                           \
        for (int _i = 0; _i < CH; ++_i) {                           \
            pa[_i] = __ldcs(_r + (size_t)_i * V_ + la);             \
            pb[_i] = __ldcs(_r + (size_t)_i * V_ + lb);             \
            pq[_i] = __ldcs(_r + (size_t)_i * V_ + (V_ - 1));       \
        }                                                           \
    } while (0)

#define LOAD_CHUNK_B(pa, pb, pq, c)                                 \
    do {                                                            \
        const float* _r = base + (size_t)(T_ - 1 - (c) * CH) * V_;  \
        _Pragma("unroll")                                           \
        for (int _i = 0; _i < CH; ++_i) {                           \
            pa[_i] = __ldcs(_r - (size_t)_i * V_ + la);             \
            pb[_i] = __ldcs(_r - (size_t)_i * V_ + lb);             \
            pq[_i] = __ldcs(_r - (size_t)_i * V_ + (V_ - 1));       \
        }                                                           \
    } while (0)

#define STEP_F(pa_, pb_, pq_)                                       \
    do {                                                            \
        float _pa = (pa_) + EPS;                                    \
        float _pb = (pb_) + EPS;                                    \
        float _pq = (pq_) + EPS;                                    \
        float _tp = __shfl_up_sync(FULL, Lb_v, 1) * corr;           \
        float _nLa = (La_v + Ba + sa * _tp) * _pa;                  \
        float _nLb = (Lb_v + Bb + sb * La_v) * _pb;                 \
        float _nBa = (Ba + _tp) * _pq;                              \
        float _nBb = (Bb + La_v) * _pq;                             \
        float _nB6 = (B64 + Lb_v) * _pq;                            \
        La_v = _nLa; Lb_v = _nLb; Ba = _nBa; Bb = _nBb; B64 = _nB6; \
    } while (0)

#define STEP_B(pa_, pb_, pq_)                                       \
    do {                                                            \
        float _pa = (pa_) + EPS;                                    \
        float _pb = (pb_) + EPS;                                    \
        float _pq = (pq_) + EPS;                                    \
        float _nb = __shfl_down_sync(FULL, Ba, 1);                  \
        float _nl = __shfl_down_sync(FULL, La_v, 1);                \
        _nb = (lane == 31) ? B64 : _nb * corr;                      \
        _nl = (lane == 31) ? 0.0f : _nl * corr;                     \
        float _nBa = (Ba + La_v) * _pq;                             \
        float _nLa = (La_v + Bb + sb * Lb_v) * _pa;                 \
        float _nBb = (Bb + Lb_v) * _pq;                             \
        float _nLb = (Lb_v + _nb + saN * _nl) * _pb;                \
        float _nB6 = B64 * _pq;                                     \
        La_v = _nLa; Lb_v = _nLb; Ba = _nBa; Bb = _nBb; B64 = _nB6; \
    } while (0)

#define RENORM_F()                                                          \
    do {                                                                    \
        float _m = fmaxf(fmaxf(fmaxf(La_v, Lb_v), fmaxf(Ba, Bb)), B64);     \
        bool _dead = (_m <= 0.0f);                                          \
        int _iexp = _dead ? 0 : (((__float_as_int(_m) >> 23) & 255) - 127); \
        if (_iexp < -120) _iexp = -120;                                     \
        int _offnew = off + _iexp;                                          \
        int _up = __shfl_up_sync(FULL, _offnew, 1);                         \
        int _offfin;                                                        \
        if (lane == 0)      _offfin = _offnew;                              \
        else if (_dead)     _offfin = _up;                                  \
        else                _offfin = (_up - MAXGAP > _offnew)              \
                                        ? (_up - MAXGAP) : _offnew;         \
        if (!_dead) {                                                       \
            float _f = exp2i(off - _offfin);                                \
            La_v *= _f; Lb_v *= _f; Ba *= _f; Bb *= _f; B64 *= _f;          \
        }                                                                   \
        off = _offfin;                                                      \
        int _upf = __shfl_up_sync(FULL, _offfin, 1);                        \
        int _dd = _upf - _offfin;                                           \
        if (_dd > 100) _dd = 100;                                           \
        corr = (lane == 0) ? 0.0f : exp2i(_dd);                             \
    } while (0)

#define RENORM_B()                                                          \
    do {                                                                    \
        float _m = fmaxf(fmaxf(fmaxf(La_v, Lb_v), fmaxf(Ba, Bb)), B64);     \
        bool _dead = (_m <= 0.0f);                                          \
        int _iexp = _dead ? 0 : (((__float_as_int(_m) >> 23) & 255) - 127); \
        if (_iexp < -120) _iexp = -120;                                     \
        int _offnew = off + _iexp;                                          \
        int _dn = __shfl_down_sync(FULL, _offnew, 1);                       \
        int _offfin;                                                        \
        if (lane == 31)     _offfin = _offnew;                              \
        else if (_dead)     _offfin = _dn;                                  \
        else                _offfin = (_dn - MAXGAP > _offnew)              \
                                        ? (_dn - MAXGAP) : _offnew;         \
        if (!_dead) {                                                       \
            float _f = exp2i(off - _offfin);                                \
            La_v *= _f; Lb_v *= _f; Ba *= _f; Bb *= _f; B64 *= _f;          \
        }                                                                   \
        off = _offfin;                                                      \
        int _dnf = __shfl_down_sync(FULL, _offfin, 1);                      \
        int _dd = _dnf - _offfin;                                           \
        if (_dd > 100) _dd = 100;                                           \
        corr = (lane == 31) ? 0.0f : exp2i(_dd);                            \
    } while (0)

    // Progress bump after finishing chunk c (DP never waits on loaders)
#define BUMP(c)  do { if (lane == 0) *vprog = (c) + 1; } while (0)

#define PROC_F(pa, pb, pq, c)                                           \
    do {                                                                \
        _Pragma("unroll")                                               \
        for (int _s = 0; _s < CH; ++_s) STEP_F(pa[_s], pb[_s], pq[_s]); \
        RENORM_F(); BUMP(c);                                            \
    } while (0)

#define PROC_B(pa, pb, pq, c)                                           \
    do {                                                                \
        _Pragma("unroll")                                               \
        for (int _s = 0; _s < CH; ++_s) STEP_B(pa[_s], pb[_s], pq[_s]); \
        RENORM_B(); BUMP(c);                                            \
    } while (0)

    if (dir == 0) {
        // -------- forward: t = 0..255 --------
        Ba = (lane == 0) ? 1.0f : 0.0f;
        La_v = Lb_v = Bb = B64 = 0.0f;
        corr = (lane == 0) ? 0.0f : 1.0f;

        LOAD_CHUNK_F(P0a, P0b, P0q, 0);
        LOAD_CHUNK_F(P1a, P1b, P1q, 1);
        LOAD_CHUNK_F(P2a, P2b, P2q, 2);
        for (int c = 0; c < NCH; c += 4) {
            if (c + 3 < NCH) LOAD_CHUNK_F(P3a, P3b, P3q, c + 3);
            PROC_F(P0a, P0b, P0q, c);
            if (c + 4 < NCH) LOAD_CHUNK_F(P0a, P0b, P0q, c + 4);
            PROC_F(P1a, P1b, P1q, c + 1);
            if (c + 5 < NCH) LOAD_CHUNK_F(P1a, P1b, P1q, c + 5);
            PROC_F(P2a, P2b, P2q, c + 2);
            if (c + 6 < NCH) LOAD_CHUNK_F(P2a, P2b, P2q, c + 6);
            PROC_F(P3a, P3b, P3q, c + 3);
        }
    } else {
        // -------- backward: t = 511..256 --------
        Ba = La_v = Bb = Lb_v = 0.0f;
        B64 = (lane == 31) ? 1.0f : 0.0f;
        corr = (lane == 31) ? 0.0f : 1.0f;

        LOAD_CHUNK_B(P0a, P0b, P0q, 0);
        LOAD_CHUNK_B(P1a, P1b, P1q, 1);
        LOAD_CHUNK_B(P2a, P2b, P2q, 2);
        for (int c = 0; c < NCH; c += 4) {
            if (c + 3 < NCH) LOAD_CHUNK_B(P3a, P3b, P3q, c + 3);
            PROC_B(P0a, P0b, P0q, c);
            if (c + 4 < NCH) LOAD_CHUNK_B(P0a, P0b, P0q, c + 4);
            PROC_B(P1a, P1b, P1q, c + 1);
            if (c + 5 < NCH) LOAD_CHUNK_B(P1a, P1b, P1q, c + 5);
            PROC_B(P2a, P2b, P2q, c + 2);
            if (c + 6 < NCH) LOAD_CHUNK_B(P2a, P2b, P2q, c + 6);
            PROC_B(P3a, P3b, P3q, c + 3);
        }

        // Publish B_{256}(s) = beta(s) + beta(s+1) + skip(s+2)*beta(s+2)
        {
            float _nb = __shfl_down_sync(FULL, Ba, 1);
            float _nl = __shfl_down_sync(FULL, La_v, 1);
            _nb = (lane == 31) ? B64 : _nb * corr;
            _nl = (lane == 31) ? 0.0f : _nl * corr;
            sBv[lane][0] = Ba + La_v;                  // B at s=4j
            sBv[lane][1] = La_v + Bb + sb * Lb_v;      // B at s=4j+1
            sBv[lane][2] = Bb + Lb_v;                  // B at s=4j+2
            sBv[lane][3] = Lb_v + _nb + saN * _nl;     // B at s=4j+3
            sBv[lane][4] = B64;                        // B at s=128
            sBo[lane] = off;
        }
    }

    __syncthreads();

    if (dir == 0) {
        // dot over this lane's states; true value = dot * 2^(offA+offB)
        float dot = Ba * sBv[lane][0] + La_v * sBv[lane][1]
                  + Bb * sBv[lane][2] + Lb_v * sBv[lane][3];
        if (lane == 31) dot += B64 * sBv[lane][4];
        int e = off + sBo[lane];

        int   ep;    // normalized exponent of lane contribution
        float m;     // mantissa in [1,2)
        if (dot > 0.0f) {
            int ie = ((__float_as_int(dot) >> 23) & 255) - 127;
            m  = dot * exp2i(-ie);
            ep = e + ie;
        } else {
            m  = 0.0f;
            ep = -0x40000000;
        }
        int emax = ep;
#pragma unroll
        for (int o = 16; o > 0; o >>= 1)
            emax = max(emax, __shfl_xor_sync(FULL, emax, o));
        float part = m * exp2i(ep - emax);
#pragma unroll
        for (int o = 16; o > 0; o >>= 1)
            part += __shfl_xor_sync(FULL, part, o);
        if (lane == 0)
            out[b] = -((__log2f(part) + (float)emax) * LN2F);
    }
}

extern "C" void kernel_launch(void* const* d_in, const int* in_sizes, int n_in,
                              void* d_out, int out_size)
{
    // Identify inputs by element count: y_true is B*L int32, y_pred is B*T*V f32
    const int* y_true = nullptr;
    const float* y_pred = nullptr;
    if (in_sizes[0] == B_ * L_) {
        y_true = (const int*)d_in[0];
        y_pred = (const float*)d_in[1];
    } else {
        y_true = (const int*)d_in[1];
        y_pred = (const float*)d_in[0];
    }
    float* out = (float*)d_out;

    // One 128-thread block per batch element:
    //   warp0 fwd DP, warp1 bwd DP, warp2 fwd loader, warp3 bwd loader
    ctc_forward_kernel<<<B_, 128>>>(y_true, y_pred, out);
}

// round 12
// speedup vs baseline: 1.2149x; 1.0234x over previous
#include <cuda_runtime.h>
#include <cstddef>
#include <cstdint>
#include <math.h>

// CTC batch cost (Keras semantics): B=256, T=512, V=256, L=64, blank=V-1
// loss[b] = -log P(y_true[b] | y_pred[b]), logp = log(y_pred + 1e-7)
//
// R12: bidirectional meet-in-the-middle DP (R8) + COALESCED full-row
// cp.async stream into a per-warp smem ring; gather moves DRAM -> SMEM.
//   Every helper-warp scheme was neutral/regressive; the binding resource
//   is chip-wide in-flight bytes, capped by ~55 LDG/warp. The gather needs
//   ~29/32 sectors of each 1KB row anyway, so: stream FULL rows with two
//   512B cp.async.cg per row (lane*16B, 4 wavefronts, depth-uncapped),
//   4-slot x 8-row private ring per DP warp (24KB outstanding/warp ->
//   ~12MB chip-wide >> 2.4MB BW*latency product), and do the label gather
//   as LDS from the ring. DRAM sees a pure sequential stream (~7.5TB/s
//   achievable) instead of scattered sectors (~5TB/s equilibrium).
//
// Block = 64 threads, one element: warp0 fwd t=0..255, warp1 bwd t=511..256.
// DP math identical to R8 (lane j owns Ba=s4j, La=s4j+1, Bb=s4j+2, Lb=s4j+3;
// lane31 B64=s128; per-lane pow2 scaling, renorm every 8 steps; combine
// P = sum_s alpha_255(s)*B_256(s) in log2 domain).

#define B_   256
#define T_   512
#define V_   256
#define L_   64
#define CH   8
#define HT   (T_ / 2)
#define NCH  (HT / CH)        // 32 chunks per direction
#define NSL  4                // ring slots per warp
#define ROWB 1040             // row stride in ring: 1024B data + 16B pad
#define SLOTB (CH * ROWB)     // 8320 B
#define RINGB (NSL * SLOTB)   // 33280 B per warp
#define SMEM_DYN (2 * RINGB)  // 66560 B per block
#define EPS  1e-7f
#define FULL 0xFFFFFFFFu
#define MAXGAP 64
#define LN2F 0.6931471805599453f

__device__ __forceinline__ float exp2i(int e)
{
    if (e <= -127) return 0.0f;
    if (e > 127)   e = 127;
    return __int_as_float((e + 127) << 23);
}

__device__ __forceinline__ void cp_async16(uint32_t saddr, const void* gaddr)
{
    asm volatile("cp.async.cg.shared.global [%0], [%1], 16;\n"
                 :: "r"(saddr), "l"(gaddr) : "memory");
}

extern __shared__ char dynsmem[];

__global__ void __launch_bounds__(64)
ctc_forward_kernel(const int* __restrict__ y_true,
                   const float* __restrict__ y_pred,
                   float* __restrict__ out)
{
    __shared__ float sBv[32][5];       // backward B-values per lane
    __shared__ int   sBo[32];          // backward off per lane

    const int b    = blockIdx.x;
    const int wid  = threadIdx.x >> 5;   // 0 = forward, 1 = backward
    const int lane = threadIdx.x & 31;
    const int dir  = wid;

    const float* base = y_pred + (size_t)b * (size_t)(T_ * V_);
    const int* lrow = y_true + b * L_;
    const int la = lrow[2 * lane];
    const int lb = lrow[2 * lane + 1];
    const int lprev = __shfl_up_sync(FULL, lb, 1);    // label[2j-1]
    const int lnext = __shfl_down_sync(FULL, la, 1);  // label[2j+2]
    const float sa  = (la != lprev) ? 1.0f : 0.0f;    // lane0 irrelevant
    const float saN = (lnext != lb) ? 1.0f : 0.0f;    // lane31 irrelevant
    const float sb  = (lb != la) ? 1.0f : 0.0f;

    // Per-warp ring
    char* ring = dynsmem + wid * RINGB;
    const uint32_t rbase = (uint32_t)__cvta_generic_to_shared(ring);
    // Row source: fwd rows 0,1,2,... ; bwd rows 511,510,...
    const char* sbase = (const char*)base
                      + (dir ? (size_t)(T_ - 1) * (V_ * 4) : 0);
    const long long srow = dir ? -(long long)(V_ * 4) : (V_ * 4);

    float Ba, La_v, Bb, Lb_v, B64;
    int   off = 0;
    float corr;
    float va[CH], vb[CH], vq[CH];

    // ---- coalesced stream of one chunk (8 full rows) into a ring slot ----
#define ISSUE_SLOT(c)                                                       \
    do {                                                                    \
        uint32_t _sp = rbase + (uint32_t)(((c) & (NSL - 1)) * SLOTB)        \
                     + (uint32_t)(lane * 16);                               \
        const char* _g = sbase + (long long)(c) * CH * srow + lane * 16;    \
        _Pragma("unroll")                                                   \
        for (int _i = 0; _i < CH; ++_i) {                                   \
            cp_async16(_sp,       _g);                                      \
            cp_async16(_sp + 512, _g + 512);                                \
            _sp += ROWB; _g += srow;                                        \
        }                                                                   \
        asm volatile("cp.async.commit_group;\n" ::: "memory");              \
    } while (0)

    // ---- gather chunk values from the ring slot into registers ----
#define READ_SLOT(c)                                                        \
    do {                                                                    \
        const char* _rp = ring + ((c) & (NSL - 1)) * SLOTB;                 \
        _Pragma("unroll")                                                   \
        for (int _i = 0; _i < CH; ++_i) {                                   \
            const float* _row = (const float*)(_rp + _i * ROWB);            \
            va[_i] = _row[la];                                              \
            vb[_i] = _row[lb];                                              \
            vq[_i] = _row[V_ - 1];                                          \
        }                                                                   \
    } while (0)

#define WAITG(n)                                                            \
    do {                                                                    \
        asm volatile("cp.async.wait_group " #n ";\n" ::: "memory");         \
        __syncwarp();                                                       \
    } while (0)

    // ---- DP steps (identical math to R8) ----
#define STEP_F(pa_, pb_, pq_)                                       \
    do {                                                            \
        float _pa = (pa_) + EPS;                                    \
        float _pb = (pb_) + EPS;                                    \
        float _pq = (pq_) + EPS;                                    \
        float _tp = __shfl_up_sync(FULL, Lb_v, 1) * corr;           \
        float _nLa = (La_v + Ba + sa * _tp) * _pa;                  \
        float _nLb = (Lb_v + Bb + sb * La_v) * _pb;                 \
        float _nBa = (Ba + _tp) * _pq;                              \
        float _nBb = (Bb + La_v) * _pq;                             \
        float _nB6 = (B64 + Lb_v) * _pq;                            \
        La_v = _nLa; Lb_v = _nLb; Ba = _nBa; Bb = _nBb; B64 = _nB6; \
    } while (0)

#define STEP_B(pa_, pb_, pq_)                                       \
    do {                                                            \
        float _pa = (pa_) + EPS;                                    \
        float _pb = (pb_) + EPS;                                    \
        float _pq = (pq_) + EPS;                                    \
        float _nb = __shfl_down_sync(FULL, Ba, 1);                  \
        float _nl = __shfl_down_sync(FULL, La_v, 1);                \
        _nb = (lane == 31) ? B64 : _nb * corr;                      \
        _nl = (lane == 31) ? 0.0f : _nl * corr;                     \
        float _nBa = (Ba + La_v) * _pq;                             \
        float _nLa = (La_v + Bb + sb * Lb_v) * _pa;                 \
        float _nBb = (Bb + Lb_v) * _pq;                             \
        float _nLb = (Lb_v + _nb + saN * _nl) * _pb;                \
        float _nB6 = B64 * _pq;                                     \
        La_v = _nLa; Lb_v = _nLb; Ba = _nBa; Bb = _nBb; B64 = _nB6; \
    } while (0)

#define RENORM_F()                                                          \
    do {                                                                    \
        float _m = fmaxf(fmaxf(fmaxf(La_v, Lb_v), fmaxf(Ba, Bb)), B64);     \
        bool _dead = (_m <= 0.0f);                                          \
        int _iexp = _dead ? 0 : (((__float_as_int(_m) >> 23) & 255) - 127); \
        if (_iexp < -120) _iexp = -120;                                     \
        int _offnew = off + _iexp;                                          \
        int _up = __shfl_up_sync(FULL, _offnew, 1);                         \
        int _offfin;                                                        \
        if (lane == 0)      _offfin = _offnew;                              \
        else if (_dead)     _offfin = _up;                                  \
        else                _offfin = (_up - MAXGAP > _offnew)              \
                                        ? (_up - MAXGAP) : _offnew;         \
        if (!_dead) {                                                       \
            float _f = exp2i(off - _offfin);                                \
            La_v *= _f; Lb_v *= _f; Ba *= _f; Bb *= _f; B64 *= _f;          \
        }                                                                   \
        off = _offfin;                                                      \
        int _upf = __shfl_up_sync(FULL, _offfin, 1);                        \
        int _dd = _upf - _offfin;                                           \
        if (_dd > 100) _dd = 100;                                           \
        corr = (lane == 0) ? 0.0f : exp2i(_dd);                             \
    } while (0)

#define RENORM_B()                                                          \
    do {                                                                    \
        float _m = fmaxf(fmaxf(fmaxf(La_v, Lb_v), fmaxf(Ba, Bb)), B64);     \
        bool _dead = (_m <= 0.0f);                                          \
        int _iexp = _dead ? 0 : (((__float_as_int(_m) >> 23) & 255) - 127); \
        if (_iexp < -120) _iexp = -120;                                     \
        int _offnew = off + _iexp;                                          \
        int _dn = __shfl_down_sync(FULL, _offnew, 1);                       \
        int _offfin;                                                        \
        if (lane == 31)     _offfin = _offnew;                              \
        else if (_dead)     _offfin = _dn;                                  \
        else                _offfin = (_dn - MAXGAP > _offnew)              \
                                        ? (_dn - MAXGAP) : _offnew;         \
        if (!_dead) {                                                       \
            float _f = exp2i(off - _offfin);                                \
            La_v *= _f; Lb_v *= _f; Ba *= _f; Bb *= _f; B64 *= _f;          \
        }                                                                   \
        off = _offfin;                                                      \
        int _dnf = __shfl_down_sync(FULL, _offfin, 1);                      \
        int _dd = _dnf - _offfin;                                           \
        if (_dd > 100) _dd = 100;                                           \
        corr = (lane == 31) ? 0.0f : exp2i(_dd);                            \
    } while (0)

#define DO_STEPS(STEPM)                                                 \
    do {                                                                \
        _Pragma("unroll")                                               \
        for (int _s = 0; _s < CH; ++_s) STEPM(va[_s], vb[_s], vq[_s]);  \
    } while (0)

    // Pipeline: prime 4 slots; steady state waits for slot c (3 younger
    // groups in flight), gathers it, refills with c+4, runs the DP chunk.
#define RUN_DIR(STEPM, RENM)                                            \
    do {                                                                \
        ISSUE_SLOT(0); ISSUE_SLOT(1); ISSUE_SLOT(2); ISSUE_SLOT(3);     \
        for (int c = 0; c <= NCH - 4; ++c) {                            \
            WAITG(3);                                                   \
            READ_SLOT(c);                                               \
            if (c + 4 < NCH) ISSUE_SLOT(c + 4);                         \
            DO_STEPS(STEPM); RENM();                                    \
        }                                                               \
        WAITG(2); READ_SLOT(NCH - 3); DO_STEPS(STEPM); RENM();          \
        WAITG(1); READ_SLOT(NCH - 2); DO_STEPS(STEPM); RENM();          \
        WAITG(0); READ_SLOT(NCH - 1); DO_STEPS(STEPM); RENM();          \
    } while (0)

    if (dir == 0) {
        // -------- forward: t = 0..255 --------
        Ba = (lane == 0) ? 1.0f : 0.0f;
        La_v = Lb_v = Bb = B64 = 0.0f;
        corr = (lane == 0) ? 0.0f : 1.0f;
        RUN_DIR(STEP_F, RENORM_F);
    } else {
        // -------- backward: t = 511..256 --------
        Ba = La_v = Bb = Lb_v = 0.0f;
        B64 = (lane == 31) ? 1.0f : 0.0f;
        corr = (lane == 31) ? 0.0f : 1.0f;
        RUN_DIR(STEP_B, RENORM_B);

        // Publish B_{256}(s) = beta(s) + beta(s+1) + skip(s+2)*beta(s+2)
        {
            float _nb = __shfl_down_sync(FULL, Ba, 1);
            float _nl = __shfl_down_sync(FULL, La_v, 1);
            _nb = (lane == 31) ? B64 : _nb * corr;
            _nl = (lane == 31) ? 0.0f : _nl * corr;
            sBv[lane][0] = Ba + La_v;                  // B at s=4j
            sBv[lane][1] = La_v + Bb + sb * Lb_v;      // B at s=4j+1
            sBv[lane][2] = Bb + Lb_v;                  // B at s=4j+2
            sBv[lane][3] = Lb_v + _nb + saN * _nl;     // B at s=4j+3
            sBv[lane][4] = B64;                        // B at s=128
            sBo[lane] = off;
        }
    }

    __syncthreads();

    if (dir == 0) {
        // dot over this lane's states; true value = dot * 2^(offA+offB)
        float dot = Ba * sBv[lane][0] + La_v * sBv[lane][1]
                  + Bb * sBv[lane][2] + Lb_v * sBv[lane][3];
        if (lane == 31) dot += B64 * sBv[lane][4];
        int e = off + sBo[lane];

        int   ep;    // normalized exponent of lane contribution
        float m;     // mantissa in [1,2)
        if (dot > 0.0f) {
            int ie = ((__float_as_int(dot) >> 23) & 255) - 127;
            m  = dot * exp2i(-ie);
            ep = e + ie;
        } else {
            m  = 0.0f;
            ep = -0x40000000;
        }
        int emax = ep;
#pragma unroll
        for (int o = 16; o > 0; o >>= 1)
            emax = max(emax, __shfl_xor_sync(FULL, emax, o));
        float part = m * exp2i(ep - emax);
#pragma unroll
        for (int o = 16; o > 0; o >>= 1)
            part += __shfl_xor_sync(FULL, part, o);
        if (lane == 0)
            out[b] = -((__log2f(part) + (float)emax) * LN2F);
    }
}

extern "C" void kernel_launch(void* const* d_in, const int* in_sizes, int n_in,
                              void* d_out, int out_size)
{
    // Identify inputs by element count: y_true is B*L int32, y_pred is B*T*V f32
    const int* y_true = nullptr;
    const float* y_pred = nullptr;
    if (in_sizes[0] == B_ * L_) {
        y_true = (const int*)d_in[0];
        y_pred = (const float*)d_in[1];
    } else {
        y_true = (const int*)d_in[1];
        y_pred = (const float*)d_in[0];
    }
    float* out = (float*)d_out;

    // 66.5KB dynamic smem ring per block (idempotent attribute set; not a
    // stream op, safe under graph capture)
    cudaFuncSetAttribute(ctc_forward_kernel,
                         cudaFuncAttributeMaxDynamicSharedMemorySize,
                         SMEM_DYN);

    // One 64-thread block per batch element: warp0 fwd DP, warp1 bwd DP
    ctc_forward_kernel<<<B_, 64, SMEM_DYN>>>(y_true, y_pred, out);
}